// round 7
// baseline (speedup 1.0000x reference)
#include <cuda_runtime.h>
#include <cuda_fp16.h>
#include <math.h>
#include <stdint.h>

#define BB   4
#define NN   10000
#define FIN  64
#define UU   64
#define EE   160000
#define CC   128
#define HID  384        // ru GEMM K
#define HCW  192        // candidate-only channels: [r*hx | A rhx | A^2 rhx]
#define NBC  (BB*NN)

// ---------------- scratch (device globals) -----------------------------------
__device__ float   g_h [BB*NN*HID];   // fp32 views for ru GEMM
__device__ float   g_hc[BB*NN*HCW];   // fp32 candidate-only views
__device__ float   g_u [BB*NN*UU];
__device__ __half2 g_f0[BB*NN*64];    // fp16: [in|hx]
__device__ __half2 g_f1[BB*NN*64];    // fp16: A[in|hx]
__device__ __half  g_c0[BB*NN*64];    // fp16: r*hx
__device__ __half2 g_c1[BB*NN*32];    // fp16: A(r*hx)
__device__ int     g_counts [NN];
__device__ int     g_offsets[NN+1];
__device__ int     g_cursor [NN];
__device__ int     g_srcs   [EE];
__device__ float   g_kers   [EE];

// ---------------- CSR build (R5-proven versions) -----------------------------
__global__ void zero_counts_k() {
    int i = blockIdx.x * blockDim.x + threadIdx.x;
    if (i < NN) g_counts[i] = 0;
}

__global__ void count_k(const int* __restrict__ dst) {
    int e = blockIdx.x * blockDim.x + threadIdx.x;
    if (e < EE) atomicAdd(&g_counts[dst[e]], 1);
}

__global__ void scan_k() {
    const int CHUNK = (NN + 1023) / 1024;  // 10
    __shared__ int sums[1024];
    int t = threadIdx.x;
    int base = t * CHUNK;
    int local[CHUNK];
    int s = 0;
    #pragma unroll
    for (int i = 0; i < CHUNK; i++) {
        int idx = base + i;
        int v = (idx < NN) ? g_counts[idx] : 0;
        local[i] = v; s += v;
    }
    sums[t] = s;
    __syncthreads();
    for (int off = 1; off < 1024; off <<= 1) {
        int v = (t >= off) ? sums[t - off] : 0;
        __syncthreads();
        sums[t] += v;
        __syncthreads();
    }
    int prefix = (t == 0) ? 0 : sums[t - 1];
    #pragma unroll
    for (int i = 0; i < CHUNK; i++) {
        int idx = base + i;
        if (idx < NN) {
            g_offsets[idx] = prefix;
            g_cursor[idx]  = prefix;
            prefix += local[i];
        }
    }
    if (t == 1023) g_offsets[NN] = sums[1023];
}

__global__ void fill_k(const int* __restrict__ src, const int* __restrict__ dst,
                       const float* __restrict__ ker) {
    int e = blockIdx.x * blockDim.x + threadIdx.x;
    if (e < EE) {
        int pos = atomicAdd(&g_cursor[dst[e]], 1);
        g_srcs[pos] = src[e];
        g_kers[pos] = ker[e];
    }
}

// ---------------- concat (R5-proven) -----------------------------------------
__global__ void concat_k(const float* __restrict__ in, const float* __restrict__ hx) {
    int idx = blockIdx.x * blockDim.x + threadIdx.x;      // over B*NN*64 half2
    if (idx >= BB*NN*64) return;
    int c2 = idx & 63;
    int bn = idx >> 6;
    float v0, v1;
    if (c2 < 32) { v0 = in[bn*FIN + c2*2];     v1 = in[bn*FIN + c2*2 + 1]; }
    else         { v0 = hx[bn*UU + (c2-32)*2]; v1 = hx[bn*UU + (c2-32)*2 + 1]; }
    g_h[bn*HID + c2*2]     = v0;
    g_h[bn*HID + c2*2 + 1] = v1;
    g_f0[idx] = __floats2half2_rn(v0, v1);
}

// ---------------- 128-wide propagation ---------------------------------------
// block = 2 nodes x 8 warps; warp = (node, batch); lane owns 2 half2 (8B load).
__global__ void prop128_k(const __half2* __restrict__ x2,   // [B][NN][64]
                          float* __restrict__ yf, int ycol,
                          __half2* __restrict__ y2) {
    int tid  = threadIdx.x;
    int n    = blockIdx.x * 2 + (tid >> 7);
    int b    = (tid >> 5) & 3;
    int lane = tid & 31;
    int s0 = g_offsets[n], s1 = g_offsets[n + 1];
    s0 = max(0, min(s0, EE)); s1 = max(s0, min(s1, EE));   // hang insurance
    const __half2* xb = x2 + (size_t)b * (NN * 64);
    float2 a0 = {0.f, 0.f}, a1 = {0.f, 0.f};
    for (int base = s0; base < s1; base += 32) {
        int cnt = min(32, s1 - base);
        int sv = 0; float kv = 0.f;
        if (lane < cnt) { sv = g_srcs[base + lane]; kv = g_kers[base + lane]; }
        for (int i = 0; i < cnt; i++) {
            int   s = __shfl_sync(0xffffffffu, sv, i);
            float k = __shfl_sync(0xffffffffu, kv, i);
            uint2 r = *(const uint2*)(xb + s * 64 + lane * 2);
            float2 v0 = __half22float2(*reinterpret_cast<__half2*>(&r.x));
            float2 v1 = __half22float2(*reinterpret_cast<__half2*>(&r.y));
            a0.x += k * v0.x; a0.y += k * v0.y;
            a1.x += k * v1.x; a1.y += k * v1.y;
        }
    }
    float4 o = make_float4(a0.x, a0.y, a1.x, a1.y);
    *(float4*)&yf[((size_t)b * NN + n) * HID + ycol + lane * 4] = o;
    if (y2) {
        __half2 p0 = __floats2half2_rn(a0.x, a0.y);
        __half2 p1 = __floats2half2_rn(a1.x, a1.y);
        uint2 pk;
        pk.x = *reinterpret_cast<uint32_t*>(&p0);
        pk.y = *reinterpret_cast<uint32_t*>(&p1);
        *(uint2*)&y2[((size_t)b * NN + n) * 64 + lane * 2] = pk;
    }
}

// ---------------- 64-wide propagation ----------------------------------------
// block = 4 nodes x 2 warps... actually: warp covers 2 batches (16 lanes each).
__global__ void prop64_k(const __half2* __restrict__ x2,    // [B][NN][32]
                         float* __restrict__ yf, int ycol,
                         __half2* __restrict__ y2) {
    int tid  = threadIdx.x;
    int n    = blockIdx.x * 4 + (tid >> 6);
    int lane = tid & 31;
    int b    = ((tid & 63) >> 4);        // 0..3 across the node's 2 warps
    int g    = tid & 15;
    int s0 = g_offsets[n], s1 = g_offsets[n + 1];
    s0 = max(0, min(s0, EE)); s1 = max(s0, min(s1, EE));   // hang insurance
    const __half2* xb = x2 + (size_t)b * (NN * 32);
    float2 a0 = {0.f, 0.f}, a1 = {0.f, 0.f};
    for (int base = s0; base < s1; base += 32) {
        int cnt = min(32, s1 - base);
        int sv = 0; float kv = 0.f;
        if (lane < cnt) { sv = g_srcs[base + lane]; kv = g_kers[base + lane]; }
        for (int i = 0; i < cnt; i++) {
            int   s = __shfl_sync(0xffffffffu, sv, i);
            float k = __shfl_sync(0xffffffffu, kv, i);
            uint2 r = *(const uint2*)(xb + s * 32 + g * 2);
            float2 v0 = __half22float2(*reinterpret_cast<__half2*>(&r.x));
            float2 v1 = __half22float2(*reinterpret_cast<__half2*>(&r.y));
            a0.x += k * v0.x; a0.y += k * v0.y;
            a1.x += k * v1.x; a1.y += k * v1.y;
        }
    }
    float4 o = make_float4(a0.x, a0.y, a1.x, a1.y);
    *(float4*)&yf[((size_t)b * NN + n) * HCW + ycol + g * 4] = o;
    if (y2) {
        __half2 p0 = __floats2half2_rn(a0.x, a0.y);
        __half2 p1 = __floats2half2_rn(a1.x, a1.y);
        uint2 pk;
        pk.x = *reinterpret_cast<uint32_t*>(&p0);
        pk.y = *reinterpret_cast<uint32_t*>(&p1);
        *(uint2*)&y2[((size_t)b * NN + n) * 32 + g * 2] = pk;
    }
}

// ---------------- tf32 mma helpers -------------------------------------------
__device__ __forceinline__ uint32_t f2tf(float x) {
    uint32_t r; asm("cvt.rna.tf32.f32 %0, %1;" : "=r"(r) : "f"(x)); return r;
}
__device__ __forceinline__ void mma8(float* c, const uint32_t* a, uint32_t b0, uint32_t b1) {
    asm volatile("mma.sync.aligned.m16n8k8.row.col.f32.tf32.tf32.f32 "
        "{%0,%1,%2,%3},{%4,%5,%6,%7},{%8,%9},{%0,%1,%2,%3};"
        : "+f"(c[0]), "+f"(c[1]), "+f"(c[2]), "+f"(c[3])
        : "r"(a[0]), "r"(a[1]), "r"(a[2]), "r"(a[3]), "r"(b0), "r"(b1));
}

#define AP   36
#define WPRU 132
#define WPC  68

// ---------------- ru GEMM (40000x128x384) + gate epilogue --------------------
__global__ void ru_mma(const float* __restrict__ W, const float* __restrict__ bias,
                       const float* __restrict__ hx) {
    __shared__ uint32_t As[64 * AP];
    __shared__ uint32_t Ws[32 * WPRU];
    int tid  = threadIdx.x;
    int lane = tid & 31, warp = tid >> 5;
    int wm = warp & 3, wn = warp >> 2;
    int gid = lane >> 2, tig = lane & 3;
    int rbase = blockIdx.x * 64;
    float acc[8][4] = {};
    for (int kt = 0; kt < HID / 32; kt++) {
        #pragma unroll
        for (int i = 0; i < 2; i++) {
            int slot = tid + i * 256;
            int r = slot >> 3, kv = slot & 7;
            float4 v = *(const float4*)&g_h[(rbase + r) * HID + kt * 32 + kv * 4];
            uint32_t* p = &As[r * AP + kv * 4];
            p[0] = f2tf(v.x); p[1] = f2tf(v.y); p[2] = f2tf(v.z); p[3] = f2tf(v.w);
        }
        #pragma unroll
        for (int i = 0; i < 4; i++) {
            int slot = tid + i * 256;
            int kr = slot >> 5, nv = slot & 31;
            float4 v = *(const float4*)&W[(kt * 32 + kr) * 128 + nv * 4];
            uint32_t* p = &Ws[kr * WPRU + nv * 4];
            p[0] = f2tf(v.x); p[1] = f2tf(v.y); p[2] = f2tf(v.z); p[3] = f2tf(v.w);
        }
        __syncthreads();
        #pragma unroll
        for (int k8 = 0; k8 < 4; k8++) {
            int ko = k8 * 8;
            uint32_t a[4];
            a[0] = As[(wm * 16 + gid    ) * AP + ko + tig];
            a[1] = As[(wm * 16 + gid + 8) * AP + ko + tig];
            a[2] = As[(wm * 16 + gid    ) * AP + ko + tig + 4];
            a[3] = As[(wm * 16 + gid + 8) * AP + ko + tig + 4];
            #pragma unroll
            for (int j = 0; j < 8; j++) {
                int n = wn * 64 + j * 8 + gid;
                uint32_t b0 = Ws[(ko + tig    ) * WPRU + n];
                uint32_t b1 = Ws[(ko + tig + 4) * WPRU + n];
                mma8(acc[j], a, b0, b1);
            }
        }
        __syncthreads();
    }
    #pragma unroll
    for (int j = 0; j < 8; j++) {
        #pragma unroll
        for (int q = 0; q < 4; q++) {
            int row = rbase + wm * 16 + gid + ((q >> 1) * 8);
            int col = wn * 64 + j * 8 + tig * 2 + (q & 1);
            float v = acc[j][q] + bias[col];
            float s = 1.f / (1.f + __expf(-v));
            if (col < UU) {
                float rv = s * hx[row * UU + col];
                g_hc[row * HCW + col] = rv;
                g_c0[row * 64 + col]  = __float2half(rv);
            } else {
                g_u[row * UU + (col - UU)] = s;
            }
        }
    }
}

// ---------------- candidate GEMM (40000x64x384) + output ---------------------
__global__ void cout_mma(const float* __restrict__ W, const float* __restrict__ bias,
                         const float* __restrict__ hx, float* __restrict__ out) {
    __shared__ uint32_t As[64 * AP];
    __shared__ uint32_t Ws[32 * WPC];
    int tid  = threadIdx.x;
    int lane = tid & 31, warp = tid >> 5;
    int wm = warp & 3, wn = warp >> 2;
    int gid = lane >> 2, tig = lane & 3;
    int rbase = blockIdx.x * 64;
    float acc[4][4] = {};
    for (int kt = 0; kt < HID / 32; kt++) {
        int pair = kt >> 1, sub = kt & 1;
        const float* srcp; int stride, colb;
        if ((pair & 1) == 0) { srcp = g_h;  stride = HID; colb = (pair >> 1) * 128 + sub * 32; }
        else                 { srcp = g_hc; stride = HCW; colb = (pair >> 1) * 64  + sub * 32; }
        #pragma unroll
        for (int i = 0; i < 2; i++) {
            int slot = tid + i * 256;
            int r = slot >> 3, kv = slot & 7;
            float4 v = *(const float4*)&srcp[(rbase + r) * stride + colb + kv * 4];
            uint32_t* p = &As[r * AP + kv * 4];
            p[0] = f2tf(v.x); p[1] = f2tf(v.y); p[2] = f2tf(v.z); p[3] = f2tf(v.w);
        }
        #pragma unroll
        for (int i = 0; i < 2; i++) {
            int slot = tid + i * 256;
            int kr = slot >> 4, nv = slot & 15;
            float4 v = *(const float4*)&W[(kt * 32 + kr) * 64 + nv * 4];
            uint32_t* p = &Ws[kr * WPC + nv * 4];
            p[0] = f2tf(v.x); p[1] = f2tf(v.y); p[2] = f2tf(v.z); p[3] = f2tf(v.w);
        }
        __syncthreads();
        #pragma unroll
        for (int k8 = 0; k8 < 4; k8++) {
            int ko = k8 * 8;
            uint32_t a[4];
            a[0] = As[(wm * 16 + gid    ) * AP + ko + tig];
            a[1] = As[(wm * 16 + gid + 8) * AP + ko + tig];
            a[2] = As[(wm * 16 + gid    ) * AP + ko + tig + 4];
            a[3] = As[(wm * 16 + gid + 8) * AP + ko + tig + 4];
            #pragma unroll
            for (int j = 0; j < 4; j++) {
                int n = wn * 32 + j * 8 + gid;
                uint32_t b0 = Ws[(ko + tig    ) * WPC + n];
                uint32_t b1 = Ws[(ko + tig + 4) * WPC + n];
                mma8(acc[j], a, b0, b1);
            }
        }
        __syncthreads();
    }
    #pragma unroll
    for (int j = 0; j < 4; j++) {
        #pragma unroll
        for (int q = 0; q < 4; q++) {
            int row = rbase + wm * 16 + gid + ((q >> 1) * 8);
            int col = wn * 32 + j * 8 + tig * 2 + (q & 1);
            float v = acc[j][q] + bias[col];
            float c = tanhf(v);
            float u = g_u[row * UU + col];
            float h = hx[row * UU + col];
            out[row * UU + col] = u * h + (1.f - u) * c;
        }
    }
}

// ---------------- launch ------------------------------------------------------
extern "C" void kernel_launch(void* const* d_in, const int* in_sizes, int n_in,
                              void* d_out, int out_size) {
    const float* inputs = (const float*)d_in[0];
    const float* hx     = (const float*)d_in[1];
    const int*   sidx   = (const int*)  d_in[2];
    const float* ker    = (const float*)d_in[3];
    const float* W_ru   = (const float*)d_in[4];
    const float* b_ru   = (const float*)d_in[5];
    const float* W_c    = (const float*)d_in[6];
    const float* b_c    = (const float*)d_in[7];
    float*       out    = (float*)d_out;

    const int* src = sidx;
    const int* dst = sidx + EE;

    zero_counts_k<<<(NN + 255) / 256, 256>>>();
    count_k<<<(EE + 255) / 256, 256>>>(dst);
    scan_k<<<1, 1024>>>();
    fill_k<<<(EE + 255) / 256, 256>>>(src, dst, ker);

    concat_k<<<(BB*NN*64 + 255) / 256, 256>>>(inputs, hx);

    float *ph, *phc; __half2 *pf0, *pf1, *pc1; __half *pc0;
    cudaGetSymbolAddress((void**)&ph,  g_h);
    cudaGetSymbolAddress((void**)&phc, g_hc);
    cudaGetSymbolAddress((void**)&pf0, g_f0);
    cudaGetSymbolAddress((void**)&pf1, g_f1);
    cudaGetSymbolAddress((void**)&pc0, g_c0);
    cudaGetSymbolAddress((void**)&pc1, g_c1);

    prop128_k<<<NN/2, 256>>>(pf0, ph, 128, pf1);
    prop128_k<<<NN/2, 256>>>(pf1, ph, 256, nullptr);

    ru_mma<<<NBC/64, 256>>>(W_ru, b_ru, hx);

    prop64_k<<<NN/4, 256>>>((const __half2*)pc0, phc, 64,  pc1);
    prop64_k<<<NN/4, 256>>>(pc1,               phc, 128, nullptr);

    cout_mma<<<NBC/64, 256>>>(W_c, b_c, hx, out);
}

// round 9
// speedup vs baseline: 1.1447x; 1.1447x over previous
#include <cuda_runtime.h>
#include <cuda_fp16.h>
#include <math.h>
#include <stdint.h>

#define BB   4
#define NN   10000
#define FIN  64
#define UU   64
#define EE   160000
#define CC   128
#define HID  384
#define NBC  (BB*NN)

// ---------------- scratch (device globals; all activations fp16) -------------
__device__ __half2 g_f0[BB*NN*64];   // [in|hx]        128ch
__device__ __half2 g_f1[BB*NN*64];   // A [in|hx]
__device__ __half2 g_f2[BB*NN*64];   // A^2 [in|hx]
__device__ __half2 g_c0[BB*NN*32];   // r*hx            64ch
__device__ __half2 g_c1[BB*NN*32];   // A (r*hx)
__device__ __half2 g_c2[BB*NN*32];   // A^2 (r*hx)
__device__ float   g_u [BB*NN*UU];   // u gate (fp32)
__device__ int     g_counts [NN];
__device__ int     g_offsets[NN+1];
__device__ int     g_cursor [NN];
__device__ int     g_srcs   [EE];
__device__ float   g_kers   [EE];

// ---------------- CSR build (proven) -----------------------------------------
__global__ void zero_counts_k() {
    int i = blockIdx.x * blockDim.x + threadIdx.x;
    if (i < NN) g_counts[i] = 0;
}

__global__ void count_k(const int* __restrict__ dst) {
    int e = blockIdx.x * blockDim.x + threadIdx.x;
    if (e < EE) atomicAdd(&g_counts[dst[e]], 1);
}

__global__ void scan_k() {
    const int CHUNK = (NN + 1023) / 1024;  // 10
    __shared__ int sums[1024];
    int t = threadIdx.x;
    int base = t * CHUNK;
    int local[CHUNK];
    int s = 0;
    #pragma unroll
    for (int i = 0; i < CHUNK; i++) {
        int idx = base + i;
        int v = (idx < NN) ? g_counts[idx] : 0;
        local[i] = v; s += v;
    }
    sums[t] = s;
    __syncthreads();
    for (int off = 1; off < 1024; off <<= 1) {
        int v = (t >= off) ? sums[t - off] : 0;
        __syncthreads();
        sums[t] += v;
        __syncthreads();
    }
    int prefix = (t == 0) ? 0 : sums[t - 1];
    #pragma unroll
    for (int i = 0; i < CHUNK; i++) {
        int idx = base + i;
        if (idx < NN) {
            g_offsets[idx] = prefix;
            g_cursor[idx]  = prefix;
            prefix += local[i];
        }
    }
    if (t == 1023) g_offsets[NN] = sums[1023];
}

__global__ void fill_k(const int* __restrict__ src, const int* __restrict__ dst,
                       const float* __restrict__ ker) {
    int e = blockIdx.x * blockDim.x + threadIdx.x;
    if (e < EE) {
        int pos = atomicAdd(&g_cursor[dst[e]], 1);
        g_srcs[pos] = src[e];
        g_kers[pos] = ker[e];
    }
}

// ---------------- concat -> f0 (fp16 only) -----------------------------------
__global__ void concat_k(const float* __restrict__ in, const float* __restrict__ hx) {
    int idx = blockIdx.x * blockDim.x + threadIdx.x;
    if (idx >= BB*NN*64) return;
    int c2 = idx & 63;
    int bn = idx >> 6;
    float v0, v1;
    if (c2 < 32) { v0 = in[bn*FIN + c2*2];     v1 = in[bn*FIN + c2*2 + 1]; }
    else         { v0 = hx[bn*UU + (c2-32)*2]; v1 = hx[bn*UU + (c2-32)*2 + 1]; }
    g_f0[idx] = __floats2half2_rn(v0, v1);
}

// ---------------- propagation helpers ----------------------------------------
__device__ __forceinline__ void fma4(float* a, uint2 r, float k) {
    float2 v0 = __half22float2(*reinterpret_cast<__half2*>(&r.x));
    float2 v1 = __half22float2(*reinterpret_cast<__half2*>(&r.y));
    a[0] += k * v0.x; a[1] += k * v0.y; a[2] += k * v1.x; a[3] += k * v1.y;
}

// 128-wide: 1 warp/node; lane owns 2 half2 (8B); 4 batch loads/edge; unroll 2.
__global__ void prop128_k(const __half2* __restrict__ x2,   // [B][NN][64]
                          __half2* __restrict__ y2) {
    const int PL = NN * 64;
    int n    = blockIdx.x * 8 + (threadIdx.x >> 5);
    int lane = threadIdx.x & 31;
    int s0 = g_offsets[n], s1 = g_offsets[n + 1];
    s0 = max(0, min(s0, EE)); s1 = max(s0, min(s1, EE));
    float acc[4][4] = {};
    for (int base = s0; base < s1; base += 32) {
        int cnt = min(32, s1 - base);
        int sv = 0; float kv = 0.f;
        if (lane < cnt) { sv = g_srcs[base + lane]; kv = g_kers[base + lane]; }
        int i = 0;
        for (; i + 1 < cnt; i += 2) {
            int   sA = __shfl_sync(~0u, sv, i);
            int   sB = __shfl_sync(~0u, sv, i + 1);
            float kA = __shfl_sync(~0u, kv, i);
            float kB = __shfl_sync(~0u, kv, i + 1);
            const __half2* pA = x2 + (size_t)sA * 64 + lane * 2;
            const __half2* pB = x2 + (size_t)sB * 64 + lane * 2;
            uint2 a0 = *(const uint2*)(pA);
            uint2 a1 = *(const uint2*)(pA + PL);
            uint2 a2 = *(const uint2*)(pA + 2*PL);
            uint2 a3 = *(const uint2*)(pA + 3*PL);
            uint2 b0 = *(const uint2*)(pB);
            uint2 b1 = *(const uint2*)(pB + PL);
            uint2 b2 = *(const uint2*)(pB + 2*PL);
            uint2 b3 = *(const uint2*)(pB + 3*PL);
            fma4(acc[0], a0, kA); fma4(acc[1], a1, kA);
            fma4(acc[2], a2, kA); fma4(acc[3], a3, kA);
            fma4(acc[0], b0, kB); fma4(acc[1], b1, kB);
            fma4(acc[2], b2, kB); fma4(acc[3], b3, kB);
        }
        if (i < cnt) {
            int   sA = __shfl_sync(~0u, sv, i);
            float kA = __shfl_sync(~0u, kv, i);
            const __half2* pA = x2 + (size_t)sA * 64 + lane * 2;
            uint2 a0 = *(const uint2*)(pA);
            uint2 a1 = *(const uint2*)(pA + PL);
            uint2 a2 = *(const uint2*)(pA + 2*PL);
            uint2 a3 = *(const uint2*)(pA + 3*PL);
            fma4(acc[0], a0, kA); fma4(acc[1], a1, kA);
            fma4(acc[2], a2, kA); fma4(acc[3], a3, kA);
        }
    }
    #pragma unroll
    for (int b = 0; b < 4; b++) {
        __half2 p0 = __floats2half2_rn(acc[b][0], acc[b][1]);
        __half2 p1 = __floats2half2_rn(acc[b][2], acc[b][3]);
        uint2 pk;
        pk.x = *reinterpret_cast<uint32_t*>(&p0);
        pk.y = *reinterpret_cast<uint32_t*>(&p1);
        *(uint2*)&y2[((size_t)b * NN + n) * 64 + lane * 2] = pk;
    }
}

// 64-wide: 1 warp/node; lane owns 1 half2 (4B); 4 batch loads/edge; unroll 2.
__global__ void prop64_k(const __half2* __restrict__ x2,    // [B][NN][32]
                         __half2* __restrict__ y2) {
    const int PL = NN * 32;
    int n    = blockIdx.x * 8 + (threadIdx.x >> 5);
    int lane = threadIdx.x & 31;
    int s0 = g_offsets[n], s1 = g_offsets[n + 1];
    s0 = max(0, min(s0, EE)); s1 = max(s0, min(s1, EE));
    float acc[4][2] = {};
    for (int base = s0; base < s1; base += 32) {
        int cnt = min(32, s1 - base);
        int sv = 0; float kv = 0.f;
        if (lane < cnt) { sv = g_srcs[base + lane]; kv = g_kers[base + lane]; }
        int i = 0;
        for (; i + 1 < cnt; i += 2) {
            int   sA = __shfl_sync(~0u, sv, i);
            int   sB = __shfl_sync(~0u, sv, i + 1);
            float kA = __shfl_sync(~0u, kv, i);
            float kB = __shfl_sync(~0u, kv, i + 1);
            const __half2* pA = x2 + (size_t)sA * 32 + lane;
            const __half2* pB = x2 + (size_t)sB * 32 + lane;
            __half2 a0 = pA[0], a1 = pA[PL], a2 = pA[2*PL], a3 = pA[3*PL];
            __half2 b0 = pB[0], b1 = pB[PL], b2 = pB[2*PL], b3 = pB[3*PL];
            float2 v;
            v = __half22float2(a0); acc[0][0] += kA*v.x; acc[0][1] += kA*v.y;
            v = __half22float2(a1); acc[1][0] += kA*v.x; acc[1][1] += kA*v.y;
            v = __half22float2(a2); acc[2][0] += kA*v.x; acc[2][1] += kA*v.y;
            v = __half22float2(a3); acc[3][0] += kA*v.x; acc[3][1] += kA*v.y;
            v = __half22float2(b0); acc[0][0] += kB*v.x; acc[0][1] += kB*v.y;
            v = __half22float2(b1); acc[1][0] += kB*v.x; acc[1][1] += kB*v.y;
            v = __half22float2(b2); acc[2][0] += kB*v.x; acc[2][1] += kB*v.y;
            v = __half22float2(b3); acc[3][0] += kB*v.x; acc[3][1] += kB*v.y;
        }
        if (i < cnt) {
            int   sA = __shfl_sync(~0u, sv, i);
            float kA = __shfl_sync(~0u, kv, i);
            const __half2* pA = x2 + (size_t)sA * 32 + lane;
            __half2 a0 = pA[0], a1 = pA[PL], a2 = pA[2*PL], a3 = pA[3*PL];
            float2 v;
            v = __half22float2(a0); acc[0][0] += kA*v.x; acc[0][1] += kA*v.y;
            v = __half22float2(a1); acc[1][0] += kA*v.x; acc[1][1] += kA*v.y;
            v = __half22float2(a2); acc[2][0] += kA*v.x; acc[2][1] += kA*v.y;
            v = __half22float2(a3); acc[3][0] += kA*v.x; acc[3][1] += kA*v.y;
        }
    }
    #pragma unroll
    for (int b = 0; b < 4; b++)
        y2[((size_t)b * NN + n) * 32 + lane] = __floats2half2_rn(acc[b][0], acc[b][1]);
}

// ---------------- tf32 mma helpers -------------------------------------------
__device__ __forceinline__ uint32_t f2tf(float x) {
    uint32_t r; asm("cvt.rna.tf32.f32 %0, %1;" : "=r"(r) : "f"(x)); return r;
}
__device__ __forceinline__ void h2_to_tf(uint32_t* p, uint2 u) {
    float2 v0 = __half22float2(*reinterpret_cast<__half2*>(&u.x));
    float2 v1 = __half22float2(*reinterpret_cast<__half2*>(&u.y));
    p[0] = f2tf(v0.x); p[1] = f2tf(v0.y); p[2] = f2tf(v1.x); p[3] = f2tf(v1.y);
}
__device__ __forceinline__ void mma8(float* c, const uint32_t* a, uint32_t b0, uint32_t b1) {
    asm volatile("mma.sync.aligned.m16n8k8.row.col.f32.tf32.tf32.f32 "
        "{%0,%1,%2,%3},{%4,%5,%6,%7},{%8,%9},{%0,%1,%2,%3};"
        : "+f"(c[0]), "+f"(c[1]), "+f"(c[2]), "+f"(c[3])
        : "r"(a[0]), "r"(a[1]), "r"(a[2]), "r"(a[3]), "r"(b0), "r"(b1));
}

#define AP   36
#define WPRU 132
#define WPC  68

// ---------------- ru GEMM (40000x128x384, A fp16) + gate epilogue ------------
__global__ void ru_mma(const float* __restrict__ W, const float* __restrict__ bias,
                       const float* __restrict__ hx) {
    __shared__ uint32_t As[64 * AP];
    __shared__ uint32_t Ws[32 * WPRU];
    int tid  = threadIdx.x;
    int lane = tid & 31, warp = tid >> 5;
    int wm = warp & 3, wn = warp >> 2;
    int gid = lane >> 2, tig = lane & 3;
    int rbase = blockIdx.x * 64;
    float acc[8][4] = {};
    for (int kt = 0; kt < HID / 32; kt++) {
        const __half2* fsrc = (kt < 4) ? g_f0 : (kt < 8 ? g_f1 : g_f2);
        int coff = (kt & 3) * 16;
        #pragma unroll
        for (int i = 0; i < 2; i++) {
            int slot = tid + i * 256;            // 0..511
            int r = slot >> 3, h = slot & 7;
            uint2 u = *(const uint2*)(fsrc + (size_t)(rbase + r) * 64 + coff + h * 2);
            h2_to_tf(&As[r * AP + h * 4], u);
        }
        #pragma unroll
        for (int i = 0; i < 4; i++) {
            int slot = tid + i * 256;
            int kr = slot >> 5, nv = slot & 31;
            float4 v = *(const float4*)&W[(kt * 32 + kr) * 128 + nv * 4];
            uint32_t* p = &Ws[kr * WPRU + nv * 4];
            p[0] = f2tf(v.x); p[1] = f2tf(v.y); p[2] = f2tf(v.z); p[3] = f2tf(v.w);
        }
        __syncthreads();
        #pragma unroll
        for (int k8 = 0; k8 < 4; k8++) {
            int ko = k8 * 8;
            uint32_t a[4];
            a[0] = As[(wm * 16 + gid    ) * AP + ko + tig];
            a[1] = As[(wm * 16 + gid + 8) * AP + ko + tig];
            a[2] = As[(wm * 16 + gid    ) * AP + ko + tig + 4];
            a[3] = As[(wm * 16 + gid + 8) * AP + ko + tig + 4];
            #pragma unroll
            for (int j = 0; j < 8; j++) {
                int n = wn * 64 + j * 8 + gid;
                uint32_t b0 = Ws[(ko + tig    ) * WPRU + n];
                uint32_t b1 = Ws[(ko + tig + 4) * WPRU + n];
                mma8(acc[j], a, b0, b1);
            }
        }
        __syncthreads();
    }
    // epilogue: wn==0 -> r gate (cols 0..63) fp16 r*hx; wn==1 -> u gate fp32
    #pragma unroll
    for (int j = 0; j < 8; j++) {
        int colb = j * 8 + tig * 2;                   // even col in [0,64)
        #pragma unroll
        for (int half = 0; half < 2; half++) {
            int row = rbase + wm * 16 + gid + half * 8;
            float v0 = acc[j][half*2 + 0];
            float v1 = acc[j][half*2 + 1];
            if (wn == 0) {
                float s0 = 1.f / (1.f + __expf(-(v0 + bias[colb])));
                float s1 = 1.f / (1.f + __expf(-(v1 + bias[colb + 1])));
                float2 h2 = *(const float2*)&hx[row * UU + colb];
                g_c0[(size_t)row * 32 + (colb >> 1)] =
                    __floats2half2_rn(s0 * h2.x, s1 * h2.y);
            } else {
                float s0 = 1.f / (1.f + __expf(-(v0 + bias[64 + colb])));
                float s1 = 1.f / (1.f + __expf(-(v1 + bias[64 + colb + 1])));
                g_u[row * UU + colb]     = s0;
                g_u[row * UU + colb + 1] = s1;
            }
        }
    }
}

// ---------------- candidate GEMM (40000x64x384, A fp16) + output -------------
__global__ void cout_mma(const float* __restrict__ W, const float* __restrict__ bias,
                         const float* __restrict__ hx, float* __restrict__ out) {
    __shared__ uint32_t As[64 * AP];
    __shared__ uint32_t Ws[32 * WPC];
    int tid  = threadIdx.x;
    int lane = tid & 31, warp = tid >> 5;
    int wm = warp & 3, wn = warp >> 2;
    int gid = lane >> 2, tig = lane & 3;
    int rbase = blockIdx.x * 64;
    float acc[4][4] = {};
    for (int kt = 0; kt < HID / 32; kt++) {
        const __half2* srcp; int rstr;
        switch (kt >> 1) {
            case 0: srcp = g_f0; rstr = 64; break;
            case 1: srcp = g_c0; rstr = 32; break;
            case 2: srcp = g_f1; rstr = 64; break;
            case 3: srcp = g_c1; rstr = 32; break;
            case 4: srcp = g_f2; rstr = 64; break;
            default: srcp = g_c2; rstr = 32; break;
        }
        int coff = (kt & 1) * 16;
        #pragma unroll
        for (int i = 0; i < 2; i++) {
            int slot = tid + i * 256;
            int r = slot >> 3, h = slot & 7;
            uint2 u = *(const uint2*)(srcp + (size_t)(rbase + r) * rstr + coff + h * 2);
            h2_to_tf(&As[r * AP + h * 4], u);
        }
        #pragma unroll
        for (int i = 0; i < 2; i++) {
            int slot = tid + i * 256;
            int kr = slot >> 4, nv = slot & 15;
            float4 v = *(const float4*)&W[(kt * 32 + kr) * 64 + nv * 4];
            uint32_t* p = &Ws[kr * WPC + nv * 4];
            p[0] = f2tf(v.x); p[1] = f2tf(v.y); p[2] = f2tf(v.z); p[3] = f2tf(v.w);
        }
        __syncthreads();
        #pragma unroll
        for (int k8 = 0; k8 < 4; k8++) {
            int ko = k8 * 8;
            uint32_t a[4];
            a[0] = As[(wm * 16 + gid    ) * AP + ko + tig];
            a[1] = As[(wm * 16 + gid + 8) * AP + ko + tig];
            a[2] = As[(wm * 16 + gid    ) * AP + ko + tig + 4];
            a[3] = As[(wm * 16 + gid + 8) * AP + ko + tig + 4];
            #pragma unroll
            for (int j = 0; j < 4; j++) {
                int n = wn * 32 + j * 8 + gid;
                uint32_t b0 = Ws[(ko + tig    ) * WPC + n];
                uint32_t b1 = Ws[(ko + tig + 4) * WPC + n];
                mma8(acc[j], a, b0, b1);
            }
        }
        __syncthreads();
    }
    #pragma unroll
    for (int j = 0; j < 4; j++) {
        #pragma unroll
        for (int q = 0; q < 4; q++) {
            int row = rbase + wm * 16 + gid + ((q >> 1) * 8);
            int col = wn * 32 + j * 8 + tig * 2 + (q & 1);
            float v = acc[j][q] + bias[col];
            float c = tanhf(v);
            float u = g_u[row * UU + col];
            float h = hx[row * UU + col];
            out[row * UU + col] = u * h + (1.f - u) * c;
        }
    }
}

// ---------------- launch ------------------------------------------------------
extern "C" void kernel_launch(void* const* d_in, const int* in_sizes, int n_in,
                              void* d_out, int out_size) {
    const float* inputs = (const float*)d_in[0];
    const float* hx     = (const float*)d_in[1];
    const int*   sidx   = (const int*)  d_in[2];
    const float* ker    = (const float*)d_in[3];
    const float* W_ru   = (const float*)d_in[4];
    const float* b_ru   = (const float*)d_in[5];
    const float* W_c    = (const float*)d_in[6];
    const float* b_c    = (const float*)d_in[7];
    float*       out    = (float*)d_out;

    const int* src = sidx;
    const int* dst = sidx + EE;

    zero_counts_k<<<(NN + 255) / 256, 256>>>();
    count_k<<<(EE + 255) / 256, 256>>>(dst);
    scan_k<<<1, 1024>>>();
    fill_k<<<(EE + 255) / 256, 256>>>(src, dst, ker);

    concat_k<<<(BB*NN*64 + 255) / 256, 256>>>(inputs, hx);

    __half2 *pf0, *pf1, *pf2, *pc0, *pc1, *pc2;
    cudaGetSymbolAddress((void**)&pf0, g_f0);
    cudaGetSymbolAddress((void**)&pf1, g_f1);
    cudaGetSymbolAddress((void**)&pf2, g_f2);
    cudaGetSymbolAddress((void**)&pc0, g_c0);
    cudaGetSymbolAddress((void**)&pc1, g_c1);
    cudaGetSymbolAddress((void**)&pc2, g_c2);

    prop128_k<<<NN/8, 256>>>(pf0, pf1);
    prop128_k<<<NN/8, 256>>>(pf1, pf2);

    ru_mma<<<NBC/64, 256>>>(W_ru, b_ru, hx);

    prop64_k<<<NN/8, 256>>>(pc0, pc1);
    prop64_k<<<NN/8, 256>>>(pc1, pc2);

    cout_mma<<<NBC/64, 256>>>(W_c, b_c, hx, out);
}

// round 10
// speedup vs baseline: 1.2406x; 1.0838x over previous
#include <cuda_runtime.h>
#include <cuda_fp16.h>
#include <math.h>
#include <stdint.h>

#define BB   4
#define NN   10000
#define FIN  64
#define UU   64
#define EE   160000
#define CC   128
#define HID  384
#define NBC  (BB*NN)

// ---------------- scratch ------------------------------------------------------
// Batch-interleaved layouts:
//   f views: __half2[NN][4][64]  (node-major, 4 batches x 64 half2 = 1024B/node)
//   c views: __half2[NN][4][32]  (512B/node)
__device__ __half2 g_f0[NN*4*64];
__device__ __half2 g_f1[NN*4*64];
__device__ __half2 g_f2[NN*4*64];
__device__ __half2 g_c0[NN*4*32];
__device__ __half2 g_c1[NN*4*32];
__device__ __half2 g_c2[NN*4*32];
__device__ float   g_u [NBC*UU];
__device__ int     g_counts [NN];
__device__ int     g_offsets[NN+1];
__device__ int     g_cursor [NN];
__device__ int     g_srcs   [EE];
__device__ float   g_kers   [EE];

// ---------------- CSR build (proven, untouched) --------------------------------
__global__ void zero_counts_k() {
    int i = blockIdx.x * blockDim.x + threadIdx.x;
    if (i < NN) g_counts[i] = 0;
}

__global__ void count_k(const int* __restrict__ dst) {
    int e = blockIdx.x * blockDim.x + threadIdx.x;
    if (e < EE) atomicAdd(&g_counts[dst[e]], 1);
}

__global__ void scan_k() {
    const int CHUNK = (NN + 1023) / 1024;  // 10
    __shared__ int sums[1024];
    int t = threadIdx.x;
    int base = t * CHUNK;
    int local[CHUNK];
    int s = 0;
    #pragma unroll
    for (int i = 0; i < CHUNK; i++) {
        int idx = base + i;
        int v = (idx < NN) ? g_counts[idx] : 0;
        local[i] = v; s += v;
    }
    sums[t] = s;
    __syncthreads();
    for (int off = 1; off < 1024; off <<= 1) {
        int v = (t >= off) ? sums[t - off] : 0;
        __syncthreads();
        sums[t] += v;
        __syncthreads();
    }
    int prefix = (t == 0) ? 0 : sums[t - 1];
    #pragma unroll
    for (int i = 0; i < CHUNK; i++) {
        int idx = base + i;
        if (idx < NN) {
            g_offsets[idx] = prefix;
            g_cursor[idx]  = prefix;
            prefix += local[i];
        }
    }
    if (t == 1023) g_offsets[NN] = sums[1023];
}

__global__ void fill_k(const int* __restrict__ src, const int* __restrict__ dst,
                       const float* __restrict__ ker) {
    int e = blockIdx.x * blockDim.x + threadIdx.x;
    if (e < EE) {
        int pos = atomicAdd(&g_cursor[dst[e]], 1);
        g_srcs[pos] = src[e];
        g_kers[pos] = ker[e];
    }
}

// ---------------- concat -> f0 (node-major interleaved) ------------------------
__global__ void concat_k(const float* __restrict__ in, const float* __restrict__ hx) {
    int idx = blockIdx.x * blockDim.x + threadIdx.x;   // over NN*4*64
    if (idx >= NN*4*64) return;
    int h = idx & 63;
    int b = (idx >> 6) & 3;
    int n = idx >> 8;
    int bn = b * NN + n;
    float v0, v1;
    if (h < 32) { v0 = in[bn*FIN + h*2];        v1 = in[bn*FIN + h*2 + 1]; }
    else        { v0 = hx[bn*UU + (h-32)*2];    v1 = hx[bn*UU + (h-32)*2 + 1]; }
    g_f0[idx] = __floats2half2_rn(v0, v1);
}

// ---------------- prop helpers -------------------------------------------------
__device__ __forceinline__ void fma8(float* a, uint4 u, float k) {
    float2 v;
    v = __half22float2(*reinterpret_cast<__half2*>(&u.x)); a[0]+=k*v.x; a[1]+=k*v.y;
    v = __half22float2(*reinterpret_cast<__half2*>(&u.y)); a[2]+=k*v.x; a[3]+=k*v.y;
    v = __half22float2(*reinterpret_cast<__half2*>(&u.z)); a[4]+=k*v.x; a[5]+=k*v.y;
    v = __half22float2(*reinterpret_cast<__half2*>(&u.w)); a[6]+=k*v.x; a[7]+=k*v.y;
}
__device__ __forceinline__ uint4 pack8(const float* a) {
    __half2 h0 = __floats2half2_rn(a[0], a[1]);
    __half2 h1 = __floats2half2_rn(a[2], a[3]);
    __half2 h2 = __floats2half2_rn(a[4], a[5]);
    __half2 h3 = __floats2half2_rn(a[6], a[7]);
    uint4 u;
    u.x = *reinterpret_cast<uint32_t*>(&h0);
    u.y = *reinterpret_cast<uint32_t*>(&h1);
    u.z = *reinterpret_cast<uint32_t*>(&h2);
    u.w = *reinterpret_cast<uint32_t*>(&h3);
    return u;
}

// 128-wide prop: warp/node; per edge = 2 contiguous LDG.128 (1024B total).
__global__ void prop128_k(const __half2* __restrict__ x2,   // [NN][4][64]
                          __half2* __restrict__ y2) {
    int n    = blockIdx.x * 8 + (threadIdx.x >> 5);
    int lane = threadIdx.x & 31;
    int s0 = g_offsets[n], s1 = g_offsets[n + 1];
    s0 = max(0, min(s0, EE)); s1 = max(s0, min(s1, EE));
    float acc0[8] = {}, acc1[8] = {};
    for (int base = s0; base < s1; base += 32) {
        int cnt = min(32, s1 - base);
        int sv = 0; float kv = 0.f;
        if (lane < cnt) { sv = g_srcs[base + lane]; kv = g_kers[base + lane]; }
        int i = 0;
        for (; i + 1 < cnt; i += 2) {
            int   sA = __shfl_sync(~0u, sv, i);
            int   sB = __shfl_sync(~0u, sv, i + 1);
            float kA = __shfl_sync(~0u, kv, i);
            float kB = __shfl_sync(~0u, kv, i + 1);
            const uint4* pA = (const uint4*)(x2 + (size_t)sA * 256) + lane;
            const uint4* pB = (const uint4*)(x2 + (size_t)sB * 256) + lane;
            uint4 a0 = pA[0], a1 = pA[32];
            uint4 b0 = pB[0], b1 = pB[32];
            fma8(acc0, a0, kA); fma8(acc1, a1, kA);
            fma8(acc0, b0, kB); fma8(acc1, b1, kB);
        }
        if (i < cnt) {
            int   sA = __shfl_sync(~0u, sv, i);
            float kA = __shfl_sync(~0u, kv, i);
            const uint4* pA = (const uint4*)(x2 + (size_t)sA * 256) + lane;
            uint4 a0 = pA[0], a1 = pA[32];
            fma8(acc0, a0, kA); fma8(acc1, a1, kA);
        }
    }
    uint4* yp = (uint4*)(y2 + (size_t)n * 256) + lane;
    yp[0]  = pack8(acc0);
    yp[32] = pack8(acc1);
}

// 64-wide prop: warp/node; per edge = 1 LDG.128 (512B); 4-edge unroll for MLP.
__global__ void prop64_k(const __half2* __restrict__ x2,    // [NN][4][32]
                         __half2* __restrict__ y2) {
    int n    = blockIdx.x * 8 + (threadIdx.x >> 5);
    int lane = threadIdx.x & 31;
    int s0 = g_offsets[n], s1 = g_offsets[n + 1];
    s0 = max(0, min(s0, EE)); s1 = max(s0, min(s1, EE));
    float acc[8] = {};
    for (int base = s0; base < s1; base += 32) {
        int cnt = min(32, s1 - base);
        int sv = 0; float kv = 0.f;
        if (lane < cnt) { sv = g_srcs[base + lane]; kv = g_kers[base + lane]; }
        int i = 0;
        for (; i + 3 < cnt; i += 4) {
            int   sA = __shfl_sync(~0u, sv, i);
            int   sB = __shfl_sync(~0u, sv, i + 1);
            int   sC = __shfl_sync(~0u, sv, i + 2);
            int   sD = __shfl_sync(~0u, sv, i + 3);
            float kA = __shfl_sync(~0u, kv, i);
            float kB = __shfl_sync(~0u, kv, i + 1);
            float kC = __shfl_sync(~0u, kv, i + 2);
            float kD = __shfl_sync(~0u, kv, i + 3);
            uint4 a = ((const uint4*)(x2 + (size_t)sA * 128))[lane];
            uint4 b = ((const uint4*)(x2 + (size_t)sB * 128))[lane];
            uint4 c = ((const uint4*)(x2 + (size_t)sC * 128))[lane];
            uint4 d = ((const uint4*)(x2 + (size_t)sD * 128))[lane];
            fma8(acc, a, kA); fma8(acc, b, kB);
            fma8(acc, c, kC); fma8(acc, d, kD);
        }
        for (; i < cnt; i++) {
            int   sA = __shfl_sync(~0u, sv, i);
            float kA = __shfl_sync(~0u, kv, i);
            uint4 a = ((const uint4*)(x2 + (size_t)sA * 128))[lane];
            fma8(acc, a, kA);
        }
    }
    ((uint4*)(y2 + (size_t)n * 128))[lane] = pack8(acc);
}

// ---------------- tf32 mma helpers ---------------------------------------------
__device__ __forceinline__ uint32_t f2tf(float x) {
    uint32_t r; asm("cvt.rna.tf32.f32 %0, %1;" : "=r"(r) : "f"(x)); return r;
}
__device__ __forceinline__ void h2_to_tf(uint32_t* p, uint2 u) {
    float2 v0 = __half22float2(*reinterpret_cast<__half2*>(&u.x));
    float2 v1 = __half22float2(*reinterpret_cast<__half2*>(&u.y));
    p[0] = f2tf(v0.x); p[1] = f2tf(v0.y); p[2] = f2tf(v1.x); p[3] = f2tf(v1.y);
}
__device__ __forceinline__ void mma8(float* c, const uint32_t* a, uint32_t b0, uint32_t b1) {
    asm volatile("mma.sync.aligned.m16n8k8.row.col.f32.tf32.tf32.f32 "
        "{%0,%1,%2,%3},{%4,%5,%6,%7},{%8,%9},{%0,%1,%2,%3};"
        : "+f"(c[0]), "+f"(c[1]), "+f"(c[2]), "+f"(c[3])
        : "r"(a[0]), "r"(a[1]), "r"(a[2]), "r"(a[3]), "r"(b0), "r"(b1));
}

#define AP   36
#define WPRU 132
#define WPC  68

// row -> (b, n) split helpers
__device__ __forceinline__ void rown(int row, int& b, int& n) {
    b = row / NN; n = row - b * NN;
}

// ---------------- ru GEMM (40000x128x384, A fp16) + gate epilogue --------------
__global__ void ru_mma(const float* __restrict__ W, const float* __restrict__ bias,
                       const float* __restrict__ hx) {
    __shared__ uint32_t As[64 * AP];
    __shared__ uint32_t Ws[32 * WPRU];
    int tid  = threadIdx.x;
    int lane = tid & 31, warp = tid >> 5;
    int wm = warp & 3, wn = warp >> 2;
    int gid = lane >> 2, tig = lane & 3;
    int rbase = blockIdx.x * 64;
    float acc[8][4] = {};
    for (int kt = 0; kt < HID / 32; kt++) {
        const __half2* fsrc = (kt < 4) ? g_f0 : (kt < 8 ? g_f1 : g_f2);
        int coff = (kt & 3) * 16;
        #pragma unroll
        for (int i = 0; i < 2; i++) {
            int slot = tid + i * 256;            // 0..511
            int r = slot >> 3, h = slot & 7;
            int b, n; rown(rbase + r, b, n);
            uint2 u = *(const uint2*)(fsrc + ((size_t)n * 4 + b) * 64 + coff + h * 2);
            h2_to_tf(&As[r * AP + h * 4], u);
        }
        #pragma unroll
        for (int i = 0; i < 4; i++) {
            int slot = tid + i * 256;
            int kr = slot >> 5, nv = slot & 31;
            float4 v = *(const float4*)&W[(kt * 32 + kr) * 128 + nv * 4];
            uint32_t* p = &Ws[kr * WPRU + nv * 4];
            p[0] = f2tf(v.x); p[1] = f2tf(v.y); p[2] = f2tf(v.z); p[3] = f2tf(v.w);
        }
        __syncthreads();
        #pragma unroll
        for (int k8 = 0; k8 < 4; k8++) {
            int ko = k8 * 8;
            uint32_t a[4];
            a[0] = As[(wm * 16 + gid    ) * AP + ko + tig];
            a[1] = As[(wm * 16 + gid + 8) * AP + ko + tig];
            a[2] = As[(wm * 16 + gid    ) * AP + ko + tig + 4];
            a[3] = As[(wm * 16 + gid + 8) * AP + ko + tig + 4];
            #pragma unroll
            for (int j = 0; j < 8; j++) {
                int n = wn * 64 + j * 8 + gid;
                uint32_t b0 = Ws[(ko + tig    ) * WPRU + n];
                uint32_t b1 = Ws[(ko + tig + 4) * WPRU + n];
                mma8(acc[j], a, b0, b1);
            }
        }
        __syncthreads();
    }
    // epilogue: wn==0 -> r gate (cols 0..63) -> g_c0 (fp16); wn==1 -> u (fp32)
    #pragma unroll
    for (int j = 0; j < 8; j++) {
        int colb = j * 8 + tig * 2;
        #pragma unroll
        for (int half = 0; half < 2; half++) {
            int row = rbase + wm * 16 + gid + half * 8;
            float v0 = acc[j][half*2 + 0];
            float v1 = acc[j][half*2 + 1];
            if (wn == 0) {
                float s0 = 1.f / (1.f + __expf(-(v0 + bias[colb])));
                float s1 = 1.f / (1.f + __expf(-(v1 + bias[colb + 1])));
                float2 h2 = *(const float2*)&hx[row * UU + colb];
                int b, n; rown(row, b, n);
                g_c0[((size_t)n * 4 + b) * 32 + (colb >> 1)] =
                    __floats2half2_rn(s0 * h2.x, s1 * h2.y);
            } else {
                float s0 = 1.f / (1.f + __expf(-(v0 + bias[64 + colb])));
                float s1 = 1.f / (1.f + __expf(-(v1 + bias[64 + colb + 1])));
                g_u[row * UU + colb]     = s0;
                g_u[row * UU + colb + 1] = s1;
            }
        }
    }
}

// ---------------- candidate GEMM (40000x64x384, A fp16) + output ---------------
__global__ void cout_mma(const float* __restrict__ W, const float* __restrict__ bias,
                         const float* __restrict__ hx, float* __restrict__ out) {
    __shared__ uint32_t As[64 * AP];
    __shared__ uint32_t Ws[32 * WPC];
    int tid  = threadIdx.x;
    int lane = tid & 31, warp = tid >> 5;
    int wm = warp & 3, wn = warp >> 2;
    int gid = lane >> 2, tig = lane & 3;
    int rbase = blockIdx.x * 64;
    float acc[4][4] = {};
    for (int kt = 0; kt < HID / 32; kt++) {
        const __half2* srcp; int rstr;
        switch (kt >> 1) {
            case 0: srcp = g_f0; rstr = 64; break;
            case 1: srcp = g_c0; rstr = 32; break;
            case 2: srcp = g_f1; rstr = 64; break;
            case 3: srcp = g_c1; rstr = 32; break;
            case 4: srcp = g_f2; rstr = 64; break;
            default: srcp = g_c2; rstr = 32; break;
        }
        int coff = (kt & 1) * 16;
        #pragma unroll
        for (int i = 0; i < 2; i++) {
            int slot = tid + i * 256;
            int r = slot >> 3, h = slot & 7;
            int b, n; rown(rbase + r, b, n);
            uint2 u = *(const uint2*)(srcp + ((size_t)n * 4 + b) * rstr + coff + h * 2);
            h2_to_tf(&As[r * AP + h * 4], u);
        }
        #pragma unroll
        for (int i = 0; i < 2; i++) {
            int slot = tid + i * 256;
            int kr = slot >> 4, nv = slot & 15;
            float4 v = *(const float4*)&W[(kt * 32 + kr) * 64 + nv * 4];
            uint32_t* p = &Ws[kr * WPC + nv * 4];
            p[0] = f2tf(v.x); p[1] = f2tf(v.y); p[2] = f2tf(v.z); p[3] = f2tf(v.w);
        }
        __syncthreads();
        #pragma unroll
        for (int k8 = 0; k8 < 4; k8++) {
            int ko = k8 * 8;
            uint32_t a[4];
            a[0] = As[(wm * 16 + gid    ) * AP + ko + tig];
            a[1] = As[(wm * 16 + gid + 8) * AP + ko + tig];
            a[2] = As[(wm * 16 + gid    ) * AP + ko + tig + 4];
            a[3] = As[(wm * 16 + gid + 8) * AP + ko + tig + 4];
            #pragma unroll
            for (int j = 0; j < 4; j++) {
                int n = wn * 32 + j * 8 + gid;
                uint32_t b0 = Ws[(ko + tig    ) * WPC + n];
                uint32_t b1 = Ws[(ko + tig + 4) * WPC + n];
                mma8(acc[j], a, b0, b1);
            }
        }
        __syncthreads();
    }
    #pragma unroll
    for (int j = 0; j < 4; j++) {
        #pragma unroll
        for (int q = 0; q < 4; q++) {
            int row = rbase + wm * 16 + gid + ((q >> 1) * 8);
            int col = wn * 32 + j * 8 + tig * 2 + (q & 1);
            float v = acc[j][q] + bias[col];
            float c = tanhf(v);
            float u = g_u[row * UU + col];
            float h = hx[row * UU + col];
            out[row * UU + col] = u * h + (1.f - u) * c;
        }
    }
}

// ---------------- launch ---------------------------------------------------------
extern "C" void kernel_launch(void* const* d_in, const int* in_sizes, int n_in,
                              void* d_out, int out_size) {
    const float* inputs = (const float*)d_in[0];
    const float* hx     = (const float*)d_in[1];
    const int*   sidx   = (const int*)  d_in[2];
    const float* ker    = (const float*)d_in[3];
    const float* W_ru   = (const float*)d_in[4];
    const float* b_ru   = (const float*)d_in[5];
    const float* W_c    = (const float*)d_in[6];
    const float* b_c    = (const float*)d_in[7];
    float*       out    = (float*)d_out;

    const int* src = sidx;
    const int* dst = sidx + EE;

    zero_counts_k<<<(NN + 255) / 256, 256>>>();
    count_k<<<(EE + 255) / 256, 256>>>(dst);
    scan_k<<<1, 1024>>>();
    fill_k<<<(EE + 255) / 256, 256>>>(src, dst, ker);

    concat_k<<<(NN*4*64 + 255) / 256, 256>>>(inputs, hx);

    __half2 *pf0, *pf1, *pf2, *pc0, *pc1, *pc2;
    cudaGetSymbolAddress((void**)&pf0, g_f0);
    cudaGetSymbolAddress((void**)&pf1, g_f1);
    cudaGetSymbolAddress((void**)&pf2, g_f2);
    cudaGetSymbolAddress((void**)&pc0, g_c0);
    cudaGetSymbolAddress((void**)&pc1, g_c1);
    cudaGetSymbolAddress((void**)&pc2, g_c2);

    prop128_k<<<NN/8, 256>>>(pf0, pf1);
    prop128_k<<<NN/8, 256>>>(pf1, pf2);

    ru_mma<<<NBC/64, 256>>>(W_ru, b_ru, hx);

    prop64_k<<<NN/8, 256>>>(pc0, pc1);
    prop64_k<<<NN/8, 256>>>(pc1, pc2);

    cout_mma<<<NBC/64, 256>>>(W_c, b_c, hx, out);
}

// round 11
// speedup vs baseline: 1.4560x; 1.1736x over previous
#include <cuda_runtime.h>
#include <cuda_fp16.h>
#include <math.h>
#include <stdint.h>

#define BB   4
#define NN   10000
#define FIN  64
#define UU   64
#define EE   160000
#define CC   128
#define HID  384
#define NBC  (BB*NN)

// ---------------- scratch ------------------------------------------------------
// Batch-interleaved: f views __half2[NN][4][64], c views __half2[NN][4][32]
__device__ __half2 g_f0[NN*4*64];
__device__ __half2 g_f1[NN*4*64];
__device__ __half2 g_f2[NN*4*64];
__device__ __half2 g_c0[NN*4*32];
__device__ __half2 g_c1[NN*4*32];
__device__ __half2 g_c2[NN*4*32];
__device__ float   g_u [NBC*UU];
__device__ int     g_counts [NN];
__device__ int     g_offsets[NN+1];
__device__ int     g_cursor [NN];
__device__ int     g_srcs   [EE];
__device__ float   g_kers   [EE];

// ---------------- CSR build (proven, untouched) --------------------------------
__global__ void zero_counts_k() {
    int i = blockIdx.x * blockDim.x + threadIdx.x;
    if (i < NN) g_counts[i] = 0;
}

__global__ void count_k(const int* __restrict__ dst) {
    int e = blockIdx.x * blockDim.x + threadIdx.x;
    if (e < EE) atomicAdd(&g_counts[dst[e]], 1);
}

__global__ void scan_k() {
    const int CHUNK = (NN + 1023) / 1024;  // 10
    __shared__ int sums[1024];
    int t = threadIdx.x;
    int base = t * CHUNK;
    int local[CHUNK];
    int s = 0;
    #pragma unroll
    for (int i = 0; i < CHUNK; i++) {
        int idx = base + i;
        int v = (idx < NN) ? g_counts[idx] : 0;
        local[i] = v; s += v;
    }
    sums[t] = s;
    __syncthreads();
    for (int off = 1; off < 1024; off <<= 1) {
        int v = (t >= off) ? sums[t - off] : 0;
        __syncthreads();
        sums[t] += v;
        __syncthreads();
    }
    int prefix = (t == 0) ? 0 : sums[t - 1];
    #pragma unroll
    for (int i = 0; i < CHUNK; i++) {
        int idx = base + i;
        if (idx < NN) {
            g_offsets[idx] = prefix;
            g_cursor[idx]  = prefix;
            prefix += local[i];
        }
    }
    if (t == 1023) g_offsets[NN] = sums[1023];
}

__global__ void fill_k(const int* __restrict__ src, const int* __restrict__ dst,
                       const float* __restrict__ ker) {
    int e = blockIdx.x * blockDim.x + threadIdx.x;
    if (e < EE) {
        int pos = atomicAdd(&g_cursor[dst[e]], 1);
        g_srcs[pos] = src[e];
        g_kers[pos] = ker[e];
    }
}

// ---------------- concat -> f0 -------------------------------------------------
__global__ void concat_k(const float* __restrict__ in, const float* __restrict__ hx) {
    int idx = blockIdx.x * blockDim.x + threadIdx.x;   // over NN*4*64
    if (idx >= NN*4*64) return;
    int h = idx & 63;
    int b = (idx >> 6) & 3;
    int n = idx >> 8;
    int bn = b * NN + n;
    float v0, v1;
    if (h < 32) { v0 = in[bn*FIN + h*2];        v1 = in[bn*FIN + h*2 + 1]; }
    else        { v0 = hx[bn*UU + (h-32)*2];    v1 = hx[bn*UU + (h-32)*2 + 1]; }
    g_f0[idx] = __floats2half2_rn(v0, v1);
}

// ---------------- prop helpers -------------------------------------------------
__device__ __forceinline__ void fma8(float* a, uint4 u, float k) {
    float2 v;
    v = __half22float2(*reinterpret_cast<__half2*>(&u.x)); a[0]+=k*v.x; a[1]+=k*v.y;
    v = __half22float2(*reinterpret_cast<__half2*>(&u.y)); a[2]+=k*v.x; a[3]+=k*v.y;
    v = __half22float2(*reinterpret_cast<__half2*>(&u.z)); a[4]+=k*v.x; a[5]+=k*v.y;
    v = __half22float2(*reinterpret_cast<__half2*>(&u.w)); a[6]+=k*v.x; a[7]+=k*v.y;
}
__device__ __forceinline__ uint4 pack8(const float* a) {
    __half2 h0 = __floats2half2_rn(a[0], a[1]);
    __half2 h1 = __floats2half2_rn(a[2], a[3]);
    __half2 h2 = __floats2half2_rn(a[4], a[5]);
    __half2 h3 = __floats2half2_rn(a[6], a[7]);
    uint4 u;
    u.x = *reinterpret_cast<uint32_t*>(&h0);
    u.y = *reinterpret_cast<uint32_t*>(&h1);
    u.z = *reinterpret_cast<uint32_t*>(&h2);
    u.w = *reinterpret_cast<uint32_t*>(&h3);
    return u;
}

// 128-wide prop: warp/node; 4-edge group -> 8 LDG.128 in flight before consume.
__global__ void prop128_k(const __half2* __restrict__ x2,   // [NN][4][64]
                          __half2* __restrict__ y2) {
    int n    = blockIdx.x * 8 + (threadIdx.x >> 5);
    int lane = threadIdx.x & 31;
    int s0 = g_offsets[n], s1 = g_offsets[n + 1];
    s0 = max(0, min(s0, EE)); s1 = max(s0, min(s1, EE));
    float acc0[8] = {}, acc1[8] = {};
    for (int base = s0; base < s1; base += 32) {
        int cnt = min(32, s1 - base);
        int sv = 0; float kv = 0.f;
        if (lane < cnt) { sv = g_srcs[base + lane]; kv = g_kers[base + lane]; }
        int i = 0;
        for (; i + 3 < cnt; i += 4) {
            int   e0 = __shfl_sync(~0u, sv, i);
            int   e1 = __shfl_sync(~0u, sv, i + 1);
            int   e2 = __shfl_sync(~0u, sv, i + 2);
            int   e3 = __shfl_sync(~0u, sv, i + 3);
            float k0 = __shfl_sync(~0u, kv, i);
            float k1 = __shfl_sync(~0u, kv, i + 1);
            float k2 = __shfl_sync(~0u, kv, i + 2);
            float k3 = __shfl_sync(~0u, kv, i + 3);
            const uint4* P0 = (const uint4*)(x2 + (size_t)e0 * 256) + lane;
            const uint4* P1 = (const uint4*)(x2 + (size_t)e1 * 256) + lane;
            const uint4* P2 = (const uint4*)(x2 + (size_t)e2 * 256) + lane;
            const uint4* P3 = (const uint4*)(x2 + (size_t)e3 * 256) + lane;
            uint4 r00 = P0[0], r01 = P0[32];
            uint4 r10 = P1[0], r11 = P1[32];
            uint4 r20 = P2[0], r21 = P2[32];
            uint4 r30 = P3[0], r31 = P3[32];
            fma8(acc0, r00, k0); fma8(acc1, r01, k0);
            fma8(acc0, r10, k1); fma8(acc1, r11, k1);
            fma8(acc0, r20, k2); fma8(acc1, r21, k2);
            fma8(acc0, r30, k3); fma8(acc1, r31, k3);
        }
        for (; i < cnt; i++) {
            int   e0 = __shfl_sync(~0u, sv, i);
            float k0 = __shfl_sync(~0u, kv, i);
            const uint4* P0 = (const uint4*)(x2 + (size_t)e0 * 256) + lane;
            uint4 r00 = P0[0], r01 = P0[32];
            fma8(acc0, r00, k0); fma8(acc1, r01, k0);
        }
    }
    uint4* yp = (uint4*)(y2 + (size_t)n * 256) + lane;
    yp[0]  = pack8(acc0);
    yp[32] = pack8(acc1);
}

// 64-wide prop: warp/node; 8-edge group -> 8 LDG.128 in flight.
__global__ void prop64_k(const __half2* __restrict__ x2,    // [NN][4][32]
                         __half2* __restrict__ y2) {
    int n    = blockIdx.x * 8 + (threadIdx.x >> 5);
    int lane = threadIdx.x & 31;
    int s0 = g_offsets[n], s1 = g_offsets[n + 1];
    s0 = max(0, min(s0, EE)); s1 = max(s0, min(s1, EE));
    float acc[8] = {};
    for (int base = s0; base < s1; base += 32) {
        int cnt = min(32, s1 - base);
        int sv = 0; float kv = 0.f;
        if (lane < cnt) { sv = g_srcs[base + lane]; kv = g_kers[base + lane]; }
        int i = 0;
        for (; i + 7 < cnt; i += 8) {
            int e[8]; float k[8];
            #pragma unroll
            for (int q = 0; q < 8; q++) {
                e[q] = __shfl_sync(~0u, sv, i + q);
                k[q] = __shfl_sync(~0u, kv, i + q);
            }
            uint4 r[8];
            #pragma unroll
            for (int q = 0; q < 8; q++)
                r[q] = ((const uint4*)(x2 + (size_t)e[q] * 128))[lane];
            #pragma unroll
            for (int q = 0; q < 8; q++) fma8(acc, r[q], k[q]);
        }
        for (; i < cnt; i++) {
            int   e0 = __shfl_sync(~0u, sv, i);
            float k0 = __shfl_sync(~0u, kv, i);
            uint4 r0 = ((const uint4*)(x2 + (size_t)e0 * 128))[lane];
            fma8(acc, r0, k0);
        }
    }
    ((uint4*)(y2 + (size_t)n * 128))[lane] = pack8(acc);
}

// ---------------- fp16 mma helpers ---------------------------------------------
__device__ __forceinline__ void mma16(float* c, const uint32_t* a, uint32_t b0, uint32_t b1) {
    asm volatile("mma.sync.aligned.m16n8k16.row.col.f32.f16.f16.f32 "
        "{%0,%1,%2,%3},{%4,%5,%6,%7},{%8,%9},{%0,%1,%2,%3};"
        : "+f"(c[0]), "+f"(c[1]), "+f"(c[2]), "+f"(c[3])
        : "r"(a[0]), "r"(a[1]), "r"(a[2]), "r"(a[3]), "r"(b0), "r"(b1));
}
__device__ __forceinline__ uint32_t packh2(float lo, float hi) {
    __half2 h = __floats2half2_rn(lo, hi);
    return *reinterpret_cast<uint32_t*>(&h);
}

#define PA   20    // As pitch (half2 = 4B words); 20 mod 32 = 4-stride rows
#define PWRU 136   // Ws pitch ru: 136 mod 32 = 8
#define PWC  72    // Ws pitch cout: 72 mod 32 = 8

__device__ __forceinline__ void rown(int row, int& b, int& n) {
    b = row / NN; n = row - b * NN;
}

// ---------------- ru GEMM (40000x128x384, fp16 mma) + gate epilogue ------------
__global__ void ru_mma(const float* __restrict__ W, const float* __restrict__ bias,
                       const float* __restrict__ hx) {
    __shared__ uint32_t As[64 * PA];      // [row][16 half2-kpairs]
    __shared__ uint32_t Ws[16 * PWRU];    // [kpair][128 cols] half2(Wk, Wk+1)
    int tid  = threadIdx.x;
    int lane = tid & 31, warp = tid >> 5;
    int wm = warp & 3, wn = warp >> 2;
    int gid = lane >> 2, tig = lane & 3;
    int rbase = blockIdx.x * 64;
    float acc[8][4] = {};
    for (int kt = 0; kt < HID / 32; kt++) {
        const __half2* fsrc = (kt < 4) ? g_f0 : (kt < 8 ? g_f1 : g_f2);
        int coff = (kt & 3) * 16;
        // A stage: raw half2 copy, 512 slots of uint2
        #pragma unroll
        for (int i = 0; i < 2; i++) {
            int slot = tid + i * 256;
            int r = slot >> 3, p = slot & 7;
            int b, n; rown(rbase + r, b, n);
            uint2 u = *(const uint2*)(fsrc + ((size_t)n * 4 + b) * 64 + coff + p * 2);
            *(uint2*)&As[r * PA + p * 2] = u;
        }
        // W stage: pack rows (2kp, 2kp+1) into half2; 512 slots
        #pragma unroll
        for (int i = 0; i < 2; i++) {
            int slot = tid + i * 256;
            int kp = slot >> 5, n4 = slot & 31;
            const float* r0 = W + (kt * 32 + kp * 2) * 128 + n4 * 4;
            float4 vA = *(const float4*)r0;
            float4 vB = *(const float4*)(r0 + 128);
            uint4 o;
            o.x = packh2(vA.x, vB.x); o.y = packh2(vA.y, vB.y);
            o.z = packh2(vA.z, vB.z); o.w = packh2(vA.w, vB.w);
            *(uint4*)&Ws[kp * PWRU + n4 * 4] = o;
        }
        __syncthreads();
        #pragma unroll
        for (int s = 0; s < 2; s++) {
            int row0 = wm * 16 + gid, row1 = row0 + 8;
            uint32_t a[4];
            a[0] = As[row0 * PA + s * 8 + tig];
            a[1] = As[row1 * PA + s * 8 + tig];
            a[2] = As[row0 * PA + s * 8 + tig + 4];
            a[3] = As[row1 * PA + s * 8 + tig + 4];
            #pragma unroll
            for (int j = 0; j < 8; j++) {
                int n = wn * 64 + j * 8 + gid;
                uint32_t b0 = Ws[(s * 8 + tig    ) * PWRU + n];
                uint32_t b1 = Ws[(s * 8 + tig + 4) * PWRU + n];
                mma16(acc[j], a, b0, b1);
            }
        }
        __syncthreads();
    }
    #pragma unroll
    for (int j = 0; j < 8; j++) {
        int colb = j * 8 + tig * 2;
        #pragma unroll
        for (int half = 0; half < 2; half++) {
            int row = rbase + wm * 16 + gid + half * 8;
            float v0 = acc[j][half*2 + 0];
            float v1 = acc[j][half*2 + 1];
            if (wn == 0) {
                float s0 = 1.f / (1.f + __expf(-(v0 + bias[colb])));
                float s1 = 1.f / (1.f + __expf(-(v1 + bias[colb + 1])));
                float2 h2 = *(const float2*)&hx[row * UU + colb];
                int b, n; rown(row, b, n);
                g_c0[((size_t)n * 4 + b) * 32 + (colb >> 1)] =
                    __floats2half2_rn(s0 * h2.x, s1 * h2.y);
            } else {
                float s0 = 1.f / (1.f + __expf(-(v0 + bias[64 + colb])));
                float s1 = 1.f / (1.f + __expf(-(v1 + bias[64 + colb + 1])));
                g_u[row * UU + colb]     = s0;
                g_u[row * UU + colb + 1] = s1;
            }
        }
    }
}

// ---------------- candidate GEMM (40000x64x384, fp16 mma) + output -------------
__global__ void cout_mma(const float* __restrict__ W, const float* __restrict__ bias,
                         const float* __restrict__ hx, float* __restrict__ out) {
    __shared__ uint32_t As[64 * PA];
    __shared__ uint32_t Ws[16 * PWC];
    int tid  = threadIdx.x;
    int lane = tid & 31, warp = tid >> 5;
    int wm = warp & 3, wn = warp >> 2;
    int gid = lane >> 2, tig = lane & 3;
    int rbase = blockIdx.x * 64;
    float acc[4][4] = {};
    for (int kt = 0; kt < HID / 32; kt++) {
        const __half2* srcp; int rstr;
        switch (kt >> 1) {
            case 0: srcp = g_f0; rstr = 64; break;
            case 1: srcp = g_c0; rstr = 32; break;
            case 2: srcp = g_f1; rstr = 64; break;
            case 3: srcp = g_c1; rstr = 32; break;
            case 4: srcp = g_f2; rstr = 64; break;
            default: srcp = g_c2; rstr = 32; break;
        }
        int coff = (kt & 1) * 16;
        #pragma unroll
        for (int i = 0; i < 2; i++) {
            int slot = tid + i * 256;
            int r = slot >> 3, p = slot & 7;
            int b, n; rown(rbase + r, b, n);
            uint2 u = *(const uint2*)(srcp + ((size_t)n * 4 + b) * rstr + coff + p * 2);
            *(uint2*)&As[r * PA + p * 2] = u;
        }
        {   // W stage: 256 slots, 1 per thread
            int kp = tid >> 4, n4 = tid & 15;
            const float* r0 = W + (kt * 32 + kp * 2) * 64 + n4 * 4;
            float4 vA = *(const float4*)r0;
            float4 vB = *(const float4*)(r0 + 64);
            uint4 o;
            o.x = packh2(vA.x, vB.x); o.y = packh2(vA.y, vB.y);
            o.z = packh2(vA.z, vB.z); o.w = packh2(vA.w, vB.w);
            *(uint4*)&Ws[kp * PWC + n4 * 4] = o;
        }
        __syncthreads();
        #pragma unroll
        for (int s = 0; s < 2; s++) {
            int row0 = wm * 16 + gid, row1 = row0 + 8;
            uint32_t a[4];
            a[0] = As[row0 * PA + s * 8 + tig];
            a[1] = As[row1 * PA + s * 8 + tig];
            a[2] = As[row0 * PA + s * 8 + tig + 4];
            a[3] = As[row1 * PA + s * 8 + tig + 4];
            #pragma unroll
            for (int j = 0; j < 4; j++) {
                int n = wn * 32 + j * 8 + gid;
                uint32_t b0 = Ws[(s * 8 + tig    ) * PWC + n];
                uint32_t b1 = Ws[(s * 8 + tig + 4) * PWC + n];
                mma16(acc[j], a, b0, b1);
            }
        }
        __syncthreads();
    }
    #pragma unroll
    for (int j = 0; j < 4; j++) {
        #pragma unroll
        for (int q = 0; q < 4; q++) {
            int row = rbase + wm * 16 + gid + ((q >> 1) * 8);
            int col = wn * 32 + j * 8 + tig * 2 + (q & 1);
            float v = acc[j][q] + bias[col];
            float c = tanhf(v);
            float u = g_u[row * UU + col];
            float h = hx[row * UU + col];
            out[row * UU + col] = u * h + (1.f - u) * c;
        }
    }
}

// ---------------- launch ---------------------------------------------------------
extern "C" void kernel_launch(void* const* d_in, const int* in_sizes, int n_in,
                              void* d_out, int out_size) {
    const float* inputs = (const float*)d_in[0];
    const float* hx     = (const float*)d_in[1];
    const int*   sidx   = (const int*)  d_in[2];
    const float* ker    = (const float*)d_in[3];
    const float* W_ru   = (const float*)d_in[4];
    const float* b_ru   = (const float*)d_in[5];
    const float* W_c    = (const float*)d_in[6];
    const float* b_c    = (const float*)d_in[7];
    float*       out    = (float*)d_out;

    const int* src = sidx;
    const int* dst = sidx + EE;

    zero_counts_k<<<(NN + 255) / 256, 256>>>();
    count_k<<<(EE + 255) / 256, 256>>>(dst);
    scan_k<<<1, 1024>>>();
    fill_k<<<(EE + 255) / 256, 256>>>(src, dst, ker);

    concat_k<<<(NN*4*64 + 255) / 256, 256>>>(inputs, hx);

    __half2 *pf0, *pf1, *pf2, *pc0, *pc1, *pc2;
    cudaGetSymbolAddress((void**)&pf0, g_f0);
    cudaGetSymbolAddress((void**)&pf1, g_f1);
    cudaGetSymbolAddress((void**)&pf2, g_f2);
    cudaGetSymbolAddress((void**)&pc0, g_c0);
    cudaGetSymbolAddress((void**)&pc1, g_c1);
    cudaGetSymbolAddress((void**)&pc2, g_c2);

    prop128_k<<<NN/8, 256>>>(pf0, pf1);
    prop128_k<<<NN/8, 256>>>(pf1, pf2);

    ru_mma<<<NBC/64, 256>>>(W_ru, b_ru, hx);

    prop64_k<<<NN/8, 256>>>(pc0, pc1);
    prop64_k<<<NN/8, 256>>>(pc1, pc2);

    cout_mma<<<NBC/64, 256>>>(W_c, b_c, hx, out);
}